// round 10
// baseline (speedup 1.0000x reference)
#include <cuda_runtime.h>

#define NV 100000
#define NE 200000
#define NF 100000
#define N_EV 400000
#define N_FE 800000
#define N_FF 800000
#define WD 128
#define NDST_TOT (NE + NF + NF)
#define NEDGE_TOT (N_EV + N_FE + N_FF)

__device__ __align__(16) float g_xv[NV * WD];   // embed_v; reused as FF0 output buffer
__device__ __align__(16) float g_xe[NE * WD];
__device__ int g_cnt[NDST_TOT];
__device__ int g_ptr[NDST_TOT];
__device__ int g_cur[NDST_TOT];
__device__ int g_bsum[256];
__device__ int g_csr[NEDGE_TOT];
__device__ unsigned g_barcnt;
__device__ volatile unsigned g_bargen;

typedef unsigned long long u64;

__device__ __forceinline__ u64 pk2(float lo, float hi) {
    u64 r; asm("mov.b64 %0, {%1,%2};" : "=l"(r) : "f"(lo), "f"(hi)); return r;
}
__device__ __forceinline__ float2 upk2(u64 v) {
    float2 r; asm("mov.b64 {%0,%1}, %2;" : "=f"(r.x), "=f"(r.y) : "l"(v)); return r;
}
// Packed fp32x2 FMA: 2x FFMA rate on sm_103a (PTX-only form).
__device__ __forceinline__ u64 ffma2(u64 a, u64 b, u64 c) {
    u64 d; asm("fma.rn.f32x2 %0, %1, %2, %3;" : "=l"(d) : "l"(a), "l"(b), "l"(c)); return d;
}
__device__ __forceinline__ void cp16(unsigned dst, const void* src, int srcsz) {
    asm volatile("cp.async.cg.shared.global [%0], [%1], 16, %2;"
                 :: "r"(dst), "l"(src), "r"(srcsz));
}
#define CP_COMMIT() asm volatile("cp.async.commit_group;")
#define CP_WAIT1()  asm volatile("cp.async.wait_group 1;")
#define CP_WAIT0()  asm volatile("cp.async.wait_group 0;")

// ---------------- software global barrier (all blocks co-resident) ----------------
__device__ __forceinline__ void gbar() {
    __syncthreads();
    if (threadIdx.x == 0) {
        unsigned gen = g_bargen;
        __threadfence();
        if (atomicAdd(&g_barcnt, 1) == gridDim.x - 1) {
            g_barcnt = 0; __threadfence(); g_bargen = gen + 1;
        } else { while (g_bargen == gen) __nanosleep(64); }
        __threadfence();
    }
    __syncthreads();
}

__device__ __forceinline__ int block_scan_incl(int v, int* tot, int* swarp) {
    int lane = threadIdx.x & 31, wid = threadIdx.x >> 5;
    int s = v;
#pragma unroll
    for (int o = 1; o < 32; o <<= 1) { int t = __shfl_up_sync(~0u, s, o); if (lane >= o) s += t; }
    if (lane == 31) swarp[wid] = s;
    __syncthreads();
    if (wid == 0) {
        int w = swarp[lane];
#pragma unroll
        for (int o = 1; o < 32; o <<= 1) { int t = __shfl_up_sync(~0u, w, o); if (lane >= o) w += t; }
        swarp[lane] = w;
    }
    __syncthreads();
    int add = (wid > 0) ? swarp[wid - 1] : 0;
    *tot = swarp[31];
    int r = s + add;
    __syncthreads();
    return r;
}

// ---------------- build all 3 CSRs in ONE kernel ----------------
__global__ void __launch_bounds__(1024)
build_csr_all(const int* __restrict__ etv_v, const int* __restrict__ etv_e,
              const int* __restrict__ fte_e, const int* __restrict__ fte_f,
              const int* __restrict__ ftf_src, const int* __restrict__ ftf_dst)
{
    __shared__ int swarp[32];
    int gtid = blockIdx.x * 1024 + threadIdx.x, gs = gridDim.x * 1024;
    for (int i = gtid; i < NDST_TOT; i += gs) g_cnt[i] = 0;
    gbar();
    for (int e = gtid; e < N_EV; e += gs) atomicAdd(&g_cnt[__ldg(etv_e + e)], 1);
    for (int e = gtid; e < N_FE; e += gs) atomicAdd(&g_cnt[NE + __ldg(fte_f + e)], 1);
    for (int e = gtid; e < N_FF; e += gs) atomicAdd(&g_cnt[NE + NF + __ldg(ftf_dst + e)], 1);
    gbar();
    const int CHUNK = (NDST_TOT + gridDim.x - 1) / gridDim.x;
    int base = blockIdx.x * CHUNK, lim = min(base + CHUNK, NDST_TOT), carry = 0;
    for (int t = base; t < base + CHUNK; t += 1024) {
        int i = t + threadIdx.x;
        int v = (i < lim) ? g_cnt[i] : 0;
        int tot; int incl = block_scan_incl(v, &tot, swarp);
        if (i < lim) g_ptr[i] = carry + incl - v;
        carry += tot;
    }
    if (threadIdx.x == 0) g_bsum[blockIdx.x] = carry;
    gbar();
    if (blockIdx.x == 0) {
        int v = ((int)threadIdx.x < (int)gridDim.x) ? g_bsum[threadIdx.x] : 0;
        int tot; int incl = block_scan_incl(v, &tot, swarp);
        if ((int)threadIdx.x < (int)gridDim.x) g_bsum[threadIdx.x] = incl - v;
    }
    gbar();
    {
        int off = g_bsum[blockIdx.x];
        for (int i = base + threadIdx.x; i < lim; i += 1024) {
            int p = g_ptr[i] + off; g_ptr[i] = p; g_cur[i] = p;
        }
    }
    gbar();
    for (int e = gtid; e < N_EV; e += gs) {
        int d = __ldg(etv_e + e);
        g_csr[atomicAdd(&g_cur[d], 1)] = __ldg(etv_v + e);
    }
    for (int e = gtid; e < N_FE; e += gs) {
        int d = NE + __ldg(fte_f + e);
        g_csr[atomicAdd(&g_cur[d], 1)] = __ldg(fte_e + e);
    }
    for (int e = gtid; e < N_FF; e += gs) {
        int d = NE + NF + __ldg(ftf_dst + e);
        g_csr[atomicAdd(&g_cur[d], 1)] = __ldg(ftf_src + e);
    }
}

// ---------------- embeddings: warp per 4 rows (LDS traffic / 4) ----------------
template<int CIN>
__global__ void embed4_kernel(const float* __restrict__ in, const float* __restrict__ Wt,
                              const float* __restrict__ bias, float* __restrict__ out, int n)
{
    __shared__ u64 sW2[CIN * 64];
    __shared__ u64 sB2[64];
    for (int i = threadIdx.x; i < CIN * 64; i += 256) sW2[i] = *(const u64*)(Wt + 2 * i);
    if (threadIdx.x < 64) sB2[threadIdx.x] = *(const u64*)(bias + 2 * threadIdx.x);
    __syncthreads();
    int w4 = (blockIdx.x * 8 + (threadIdx.x >> 5)) * 4;
    if (w4 >= n) return;
    int lane = threadIdx.x & 31;
    // load 4*CIN inputs across the warp (<=56 floats in 2 passes)
    float x0 = 0.f, x1 = 0.f;
    {
        long long b = (long long)w4 * CIN;
        long long tot = (long long)n * CIN;
        if (lane < 4 * CIN && b + lane < tot) x0 = __ldg(in + b + lane);
        if (32 + lane < 4 * CIN && b + 32 + lane < tot) x1 = __ldg(in + b + 32 + lane);
    }
    u64 a[4][2];
#pragma unroll
    for (int r = 0; r < 4; r++) { a[r][0] = sB2[2 * lane]; a[r][1] = sB2[2 * lane + 1]; }
#pragma unroll
    for (int k = 0; k < CIN; k++) {
        u64 w0 = sW2[k * 64 + 2 * lane], w1 = sW2[k * 64 + 2 * lane + 1];
#pragma unroll
        for (int r = 0; r < 4; r++) {
            int p = r * CIN + k;
            float xk = (p < 32) ? __shfl_sync(~0u, x0, p) : __shfl_sync(~0u, x1, p - 32);
            u64 h2 = pk2(xk, xk);
            a[r][0] = ffma2(h2, w0, a[r][0]);
            a[r][1] = ffma2(h2, w1, a[r][1]);
        }
    }
#pragma unroll
    for (int r = 0; r < 4; r++) {
        int row = w4 + r;
        if (row < n) {
            float2 v0 = upk2(a[r][0]), v1 = upk2(a[r][1]);
            float4 o;
            o.x = v0.x > 0.f ? v0.x : 0.01f * v0.x;
            o.y = v0.y > 0.f ? v0.y : 0.01f * v0.y;
            o.z = v1.x > 0.f ? v1.x : 0.01f * v1.x;
            o.w = v1.y > 0.f ? v1.y : 0.01f * v1.y;
            *(float4*)(out + (size_t)row * WD + lane * 4) = o;
        }
    }
}

// ---------------- fused conv: gather-min + GEMM + residual, one kernel ----------------
// out = xdst + lrelu([xdst | xdst - segmin(xsrc)] @ Wm + bm)
// 256 threads, 128-row tile. SMEM floats:
//   sW  [2][64][128]  (double-buffered W chunks)
//   sB  [128]
//   sH  [2][128][68]  (xdst k0-63 / k64-127; persists for residual)
//   sM  [2][128][68]  (gathered maxes dims 0-63 / 64-127; reused as epilogue stage)
#define CONV_THREADS 256
#define TILE_R 128
#define HSTR 68
#define WCH 8192
#define SB_OFF (2 * WCH)          // 16384
#define SH_OFF (SB_OFF + 128)     // 16512
#define SM_OFF (SH_OFF + 17408)   // 33920
#define CONV_SMEM ((SM_OFF + 17408) * 4)   // 205312 B

__global__ void __launch_bounds__(CONV_THREADS, 1)
conv_fused(const float* __restrict__ xsrc, const float* __restrict__ xdst,
           const int* __restrict__ ptr, const int* __restrict__ cnt,
           const int* __restrict__ csr,
           const float* __restrict__ Wm, const float* __restrict__ bm,
           float* __restrict__ out, int n)
{
    extern __shared__ float smem[];
    float* sB = smem + SB_OFF;
    unsigned sWa = (unsigned)__cvta_generic_to_shared(smem);
    unsigned sHa = (unsigned)__cvta_generic_to_shared(smem + SH_OFF);

    int tid = threadIdx.x, wid = tid >> 5, lane = tid & 31;
    int row0 = blockIdx.x * TILE_R;

    // prologue: W0+h0 (group), W1+h1 (group)
#pragma unroll 1
    for (int b = 0; b < 2; b++) {
        const char* wsrc = (const char*)Wm + (size_t)b * WCH * 4;
        unsigned wb = sWa + b * WCH * 4;
#pragma unroll
        for (int t = 0; t < 8; t++) {
            int u = tid + t * 256;
            cp16(wb + u * 16, wsrc + u * 16, 16);
        }
        const char* hs = (const char*)xdst + b * 256;
        unsigned hb = sHa + b * 8704 * 4;
#pragma unroll
        for (int t = 0; t < 8; t++) {
            int idx = tid + t * 256;
            int row = idx >> 4, u = idx & 15;
            int sz = (row0 + row < n) ? 16 : 0;
            cp16(hb + row * HSTR * 4 + u * 16, hs + (size_t)(row0 + row) * 512 + u * 16, sz);
        }
        CP_COMMIT();
    }
    if (tid < WD) sB[tid] = bm[tid];

    // gather phase: warp wid owns rows [wid*16, wid*16+16); store raw segmin to sM
    const float inf = __int_as_float(0x7f800000);
    {
        int p = lane >> 4, col = (4 * lane) & 63;
        float* mslot = smem + SM_OFF + p * 8704 + col;
#pragma unroll 1
        for (int rr = 0; rr < 16; rr++) {
            int lrow = wid * 16 + rr, grow = row0 + lrow;
            float4 mn = make_float4(inf, inf, inf, inf);
            if (grow < n) {
                int deg = __ldg(cnt + grow), base = __ldg(ptr + grow);
                int i = 0;
                for (; i + 4 <= deg; i += 4) {
                    int s0 = __ldg(csr + base + i), s1 = __ldg(csr + base + i + 1);
                    int s2 = __ldg(csr + base + i + 2), s3 = __ldg(csr + base + i + 3);
                    float4 v0 = __ldg((const float4*)(xsrc + (size_t)s0 * WD) + lane);
                    float4 v1 = __ldg((const float4*)(xsrc + (size_t)s1 * WD) + lane);
                    float4 v2 = __ldg((const float4*)(xsrc + (size_t)s2 * WD) + lane);
                    float4 v3 = __ldg((const float4*)(xsrc + (size_t)s3 * WD) + lane);
                    mn.x = fminf(mn.x, fminf(fminf(v0.x, v1.x), fminf(v2.x, v3.x)));
                    mn.y = fminf(mn.y, fminf(fminf(v0.y, v1.y), fminf(v2.y, v3.y)));
                    mn.z = fminf(mn.z, fminf(fminf(v0.z, v1.z), fminf(v2.z, v3.z)));
                    mn.w = fminf(mn.w, fminf(fminf(v0.w, v1.w), fminf(v2.w, v3.w)));
                }
                for (; i < deg; i++) {
                    int s = __ldg(csr + base + i);
                    float4 v = __ldg((const float4*)(xsrc + (size_t)s * WD) + lane);
                    mn.x = fminf(mn.x, v.x); mn.y = fminf(mn.y, v.y);
                    mn.z = fminf(mn.z, v.z); mn.w = fminf(mn.w, v.w);
                }
            }
            *(float4*)(mslot + lrow * HSTR) = mn;
        }
    }
    CP_WAIT0();
    __syncthreads();
    // diff pass: sM = (deg>0) ? sH - sM : 0   (deg==0 <=> min stayed +inf)
#pragma unroll 1
    for (int idx = tid; idx < 4096; idx += CONV_THREADS) {
        int row = idx >> 5, l = idx & 31;
        int p = l >> 4, col = (4 * l) & 63;
        float* ma = smem + SM_OFF + p * 8704 + row * HSTR + col;
        const float* ha = smem + SH_OFF + p * 8704 + row * HSTR + col;
        float4 mn = *(float4*)ma;
        float4 h = *(const float4*)ha;
        float4 o;
        if (__float_as_int(mn.x) == 0x7f800000) {
            o = make_float4(0.f, 0.f, 0.f, 0.f);
        } else {
            o = make_float4(h.x - mn.x, h.y - mn.y, h.z - mn.z, h.w - mn.w);
        }
        *(float4*)ma = o;
    }
    __syncthreads();

    // GEMM: chunks c0(sH0,W0) c1(sH1,W1) c2(sM0,W2) c3(sM1,W3)
    int rg = tid >> 3;      // 0..31 -> rows rg*4..rg*4+3
    int cgp = tid & 7;      // col pairs cgp + 8*cc
    u64 acc[4][8];
    {
        const u64* sB2 = (const u64*)sB;
#pragma unroll
        for (int cc = 0; cc < 8; cc++) {
            u64 b2 = sB2[cgp + 8 * cc];
#pragma unroll
            for (int r = 0; r < 4; r++) acc[r][cc] = b2;
        }
    }
#pragma unroll 1
    for (int c = 0; c < 4; c++) {
        if (c == 2) { CP_WAIT1(); __syncthreads(); }
        if (c == 3) { CP_WAIT0(); __syncthreads(); }
        const u64* sWc = (const u64*)(smem + (c & 1) * WCH);
        const float* hb = smem + (c < 2 ? SH_OFF : SM_OFF) + (c & 1) * 8704 + (rg * 4) * HSTR;
#pragma unroll 1
        for (int k4 = 0; k4 < 16; k4++) {
            float4 h4[4];
#pragma unroll
            for (int r = 0; r < 4; r++) h4[r] = *(const float4*)(hb + r * HSTR + k4 * 4);
#pragma unroll
            for (int kk = 0; kk < 4; kk++) {
                const u64* wr = sWc + (k4 * 4 + kk) * 64 + cgp;
                u64 w[8];
#pragma unroll
                for (int cc = 0; cc < 8; cc++) w[cc] = wr[8 * cc];
#pragma unroll
                for (int r = 0; r < 4; r++) {
                    float hv = (kk == 0) ? h4[r].x : (kk == 1) ? h4[r].y
                             : (kk == 2) ? h4[r].z : h4[r].w;
                    u64 h2 = pk2(hv, hv);
#pragma unroll
                    for (int cc = 0; cc < 8; cc++) acc[r][cc] = ffma2(h2, w[cc], acc[r][cc]);
                }
            }
        }
        __syncthreads();
        if (c == 0) {   // prefetch W2 -> buf0
            const char* wsrc = (const char*)Wm + (size_t)2 * WCH * 4;
#pragma unroll
            for (int t = 0; t < 8; t++) {
                int u = tid + t * 256;
                cp16(sWa + u * 16, wsrc + u * 16, 16);
            }
            CP_COMMIT();
        }
        if (c == 1) {   // prefetch W3 -> buf1
            const char* wsrc = (const char*)Wm + (size_t)3 * WCH * 4;
#pragma unroll
            for (int t = 0; t < 8; t++) {
                int u = tid + t * 256;
                cp16(sWa + WCH * 4 + u * 16, wsrc + u * 16, 16);
            }
            CP_COMMIT();
        }
    }

    // epilogue: lrelu -> sO stage (sM region, free now), residual from sH, coalesced store
    float* sO = smem + SM_OFF;   // [128][132]
#pragma unroll
    for (int r = 0; r < 4; r++) {
        int lrow = rg * 4 + r;
#pragma unroll
        for (int cc = 0; cc < 8; cc++) {
            float2 v = upk2(acc[r][cc]);
            float2 a;
            a.x = v.x > 0.f ? v.x : 0.01f * v.x;
            a.y = v.y > 0.f ? v.y : 0.01f * v.y;
            *(float2*)(sO + lrow * 132 + 2 * (cgp + 8 * cc)) = a;
        }
    }
    __syncthreads();
#pragma unroll 1
    for (int idx = tid; idx < TILE_R * 32; idx += CONV_THREADS) {
        int row = idx >> 5, c4 = idx & 31;
        int grow = row0 + row;
        if (grow < n) {
            float4 o = *(const float4*)(sO + row * 132 + c4 * 4);
            const float* ha = smem + SH_OFF + (c4 >> 4) * 8704 + row * HSTR + ((4 * c4) & 63);
            float4 x = *(const float4*)ha;
            float4 res = make_float4(x.x + o.x, x.y + o.y, x.z + o.z, x.w + o.w);
            *((float4*)(out + (size_t)grow * WD) + c4) = res;
        }
    }
}

// ---------------- launch ----------------
extern "C" void kernel_launch(void* const* d_in, const int* in_sizes, int n_in,
                              void* d_out, int out_size)
{
    const float* vertices = (const float*)d_in[0];
    const float* edges    = (const float*)d_in[1];
    const float* faces    = (const float*)d_in[2];
    const int* etv_v   = (const int*)d_in[3];
    const int* etv_e   = (const int*)d_in[4];
    const int* fte_e   = (const int*)d_in[5];
    const int* fte_f   = (const int*)d_in[6];
    const int* ftf_src = (const int*)d_in[7];
    const int* ftf_dst = (const int*)d_in[8];
    const float* Wv   = (const float*)d_in[9];
    const float* bv   = (const float*)d_in[10];
    const float* We   = (const float*)d_in[11];
    const float* be   = (const float*)d_in[12];
    const float* Wf   = (const float*)d_in[13];
    const float* bf   = (const float*)d_in[14];
    const float* Wv2e = (const float*)d_in[15];
    const float* bv2e = (const float*)d_in[16];
    const float* We2f = (const float*)d_in[17];
    const float* be2f = (const float*)d_in[18];
    const float* Wm0  = (const float*)d_in[19];
    const float* bm0  = (const float*)d_in[20];
    const float* Wm1  = (const float*)d_in[21];
    const float* bm1  = (const float*)d_in[22];

    float *xv, *xe;
    int *cnt, *ptr, *csr;
    cudaGetSymbolAddress((void**)&xv, g_xv);
    cudaGetSymbolAddress((void**)&xe, g_xe);
    cudaGetSymbolAddress((void**)&cnt, g_cnt);
    cudaGetSymbolAddress((void**)&ptr, g_ptr);
    cudaGetSymbolAddress((void**)&csr, g_csr);
    float* xf = (float*)d_out;

    cudaFuncSetAttribute(conv_fused, cudaFuncAttributeMaxDynamicSharedMemorySize, CONV_SMEM);

    // 0: all 3 CSRs (index-only)
    build_csr_all<<<148, 1024>>>(etv_v, etv_e, fte_e, fte_f, ftf_src, ftf_dst);

    // 1-3: embeddings
    embed4_kernel<3><<<(NV + 31) / 32, 256>>>(vertices, Wv, bv, xv, NV);
    embed4_kernel<12><<<(NE + 31) / 32, 256>>>(edges, We, be, xe, NE);
    embed4_kernel<14><<<(NF + 31) / 32, 256>>>(faces, Wf, bf, xf, NF);

    // 4: V2E (src=xv, dst=xe, in-place own-rows)
    conv_fused<<<(NE + TILE_R - 1) / TILE_R, CONV_THREADS, CONV_SMEM>>>(
        xv, xe, ptr, cnt, csr, Wv2e, bv2e, xe, NE);

    // 5: E2F (src=xe, dst=xf, in-place own-rows)
    conv_fused<<<(NF + TILE_R - 1) / TILE_R, CONV_THREADS, CONV_SMEM>>>(
        xe, xf, ptr + NE, cnt + NE, csr, We2f, be2f, xf, NF);

    // 6: FF layer 0 (src=dst=xf; out -> xv buffer to avoid cross-block race)
    conv_fused<<<(NF + TILE_R - 1) / TILE_R, CONV_THREADS, CONV_SMEM>>>(
        xf, xf, ptr + NE + NF, cnt + NE + NF, csr, Wm0, bm0, xv, NF);

    // 7: FF layer 1 (src=dst=xv buffer; out -> d_out)
    conv_fused<<<(NF + TILE_R - 1) / TILE_R, CONV_THREADS, CONV_SMEM>>>(
        xv, xv, ptr + NE + NF, cnt + NE + NF, csr, Wm1, bm1, xf, NF);
}

// round 12
// speedup vs baseline: 1.5022x; 1.5022x over previous
#include <cuda_runtime.h>

#define NV 100000
#define NE 200000
#define NF 100000
#define N_EV 400000
#define N_FE 800000
#define N_FF 800000
#define WD 128
#define NDST_TOT (NE + NF + NF)
#define NEDGE_TOT (N_EV + N_FE + N_FF)

__device__ __align__(16) float g_xv[NV * WD];
__device__ __align__(16) float g_xe[NE * WD];
__device__ __align__(16) float g_max[NE * WD];
__device__ int g_cnt[NDST_TOT];
__device__ int g_ptr[NDST_TOT];
__device__ int g_cur[NDST_TOT];
__device__ int g_bsum[256];
__device__ int g_csr[NEDGE_TOT];
__device__ unsigned g_barcnt;
__device__ volatile unsigned g_bargen;

typedef unsigned long long u64;

__device__ __forceinline__ u64 pk2(float lo, float hi) {
    u64 r; asm("mov.b64 %0, {%1,%2};" : "=l"(r) : "f"(lo), "f"(hi)); return r;
}
__device__ __forceinline__ float2 upk2(u64 v) {
    float2 r; asm("mov.b64 {%0,%1}, %2;" : "=f"(r.x), "=f"(r.y) : "l"(v)); return r;
}
// Packed fp32x2 FMA: 2x FFMA rate on sm_103a (PTX-only form).
__device__ __forceinline__ u64 ffma2(u64 a, u64 b, u64 c) {
    u64 d; asm("fma.rn.f32x2 %0, %1, %2, %3;" : "=l"(d) : "l"(a), "l"(b), "l"(c)); return d;
}
__device__ __forceinline__ void cp16(unsigned dst, const void* src, int srcsz) {
    asm volatile("cp.async.cg.shared.global [%0], [%1], 16, %2;"
                 :: "r"(dst), "l"(src), "r"(srcsz));
}
#define CP_COMMIT() asm volatile("cp.async.commit_group;")
#define CP_WAIT1()  asm volatile("cp.async.wait_group 1;")
#define CP_WAIT0()  asm volatile("cp.async.wait_group 0;")

// ---------------- software global barrier ----------------
__device__ __forceinline__ void gbar() {
    __syncthreads();
    if (threadIdx.x == 0) {
        unsigned gen = g_bargen;
        __threadfence();
        if (atomicAdd(&g_barcnt, 1) == gridDim.x - 1) {
            g_barcnt = 0; __threadfence(); g_bargen = gen + 1;
        } else { while (g_bargen == gen) __nanosleep(64); }
        __threadfence();
    }
    __syncthreads();
}

__device__ __forceinline__ int block_scan_incl(int v, int* tot, int* swarp) {
    int lane = threadIdx.x & 31, wid = threadIdx.x >> 5;
    int s = v;
#pragma unroll
    for (int o = 1; o < 32; o <<= 1) { int t = __shfl_up_sync(~0u, s, o); if (lane >= o) s += t; }
    if (lane == 31) swarp[wid] = s;
    __syncthreads();
    if (wid == 0) {
        int w = swarp[lane];
#pragma unroll
        for (int o = 1; o < 32; o <<= 1) { int t = __shfl_up_sync(~0u, w, o); if (lane >= o) w += t; }
        swarp[lane] = w;
    }
    __syncthreads();
    int add = (wid > 0) ? swarp[wid - 1] : 0;
    *tot = swarp[31];
    int r = s + add;
    __syncthreads();
    return r;
}

// ---------------- build all 3 CSRs in ONE kernel ----------------
__global__ void __launch_bounds__(1024)
build_csr_all(const int* __restrict__ etv_v, const int* __restrict__ etv_e,
              const int* __restrict__ fte_e, const int* __restrict__ fte_f,
              const int* __restrict__ ftf_src, const int* __restrict__ ftf_dst)
{
    __shared__ int swarp[32];
    int gtid = blockIdx.x * 1024 + threadIdx.x, gs = gridDim.x * 1024;
    for (int i = gtid; i < NDST_TOT; i += gs) g_cnt[i] = 0;
    gbar();
    for (int e = gtid; e < N_EV; e += gs) atomicAdd(&g_cnt[__ldg(etv_e + e)], 1);
    for (int e = gtid; e < N_FE; e += gs) atomicAdd(&g_cnt[NE + __ldg(fte_f + e)], 1);
    for (int e = gtid; e < N_FF; e += gs) atomicAdd(&g_cnt[NE + NF + __ldg(ftf_dst + e)], 1);
    gbar();
    const int CHUNK = (NDST_TOT + gridDim.x - 1) / gridDim.x;
    int base = blockIdx.x * CHUNK, lim = min(base + CHUNK, NDST_TOT), carry = 0;
    for (int t = base; t < base + CHUNK; t += 1024) {
        int i = t + threadIdx.x;
        int v = (i < lim) ? g_cnt[i] : 0;
        int tot; int incl = block_scan_incl(v, &tot, swarp);
        if (i < lim) g_ptr[i] = carry + incl - v;
        carry += tot;
    }
    if (threadIdx.x == 0) g_bsum[blockIdx.x] = carry;
    gbar();
    if (blockIdx.x == 0) {
        int v = ((int)threadIdx.x < (int)gridDim.x) ? g_bsum[threadIdx.x] : 0;
        int tot; int incl = block_scan_incl(v, &tot, swarp);
        if ((int)threadIdx.x < (int)gridDim.x) g_bsum[threadIdx.x] = incl - v;
    }
    gbar();
    {
        int off = g_bsum[blockIdx.x];
        for (int i = base + threadIdx.x; i < lim; i += 1024) {
            int p = g_ptr[i] + off; g_ptr[i] = p; g_cur[i] = p;
        }
    }
    gbar();
    for (int e = gtid; e < N_EV; e += gs) {
        int d = __ldg(etv_e + e);
        g_csr[atomicAdd(&g_cur[d], 1)] = __ldg(etv_v + e);
    }
    for (int e = gtid; e < N_FE; e += gs) {
        int d = NE + __ldg(fte_f + e);
        g_csr[atomicAdd(&g_cur[d], 1)] = __ldg(fte_e + e);
    }
    for (int e = gtid; e < N_FF; e += gs) {
        int d = NE + NF + __ldg(ftf_dst + e);
        g_csr[atomicAdd(&g_cur[d], 1)] = __ldg(ftf_src + e);
    }
}

// ---------------- embeddings: warp per 4 rows ----------------
template<int CIN>
__global__ void embed4_kernel(const float* __restrict__ in, const float* __restrict__ Wt,
                              const float* __restrict__ bias, float* __restrict__ out, int n)
{
    __shared__ u64 sW2[CIN * 64];
    __shared__ u64 sB2[64];
    for (int i = threadIdx.x; i < CIN * 64; i += 256) sW2[i] = *(const u64*)(Wt + 2 * i);
    if (threadIdx.x < 64) sB2[threadIdx.x] = *(const u64*)(bias + 2 * threadIdx.x);
    __syncthreads();
    int w4 = (blockIdx.x * 8 + (threadIdx.x >> 5)) * 4;
    if (w4 >= n) return;
    int lane = threadIdx.x & 31;
    float x0 = 0.f, x1 = 0.f;
    {
        long long b = (long long)w4 * CIN;
        long long tot = (long long)n * CIN;
        if (lane < 4 * CIN && b + lane < tot) x0 = __ldg(in + b + lane);
        if (32 + lane < 4 * CIN && b + 32 + lane < tot) x1 = __ldg(in + b + 32 + lane);
    }
    u64 a[4][2];
#pragma unroll
    for (int r = 0; r < 4; r++) { a[r][0] = sB2[2 * lane]; a[r][1] = sB2[2 * lane + 1]; }
#pragma unroll
    for (int k = 0; k < CIN; k++) {
        u64 w0 = sW2[k * 64 + 2 * lane], w1 = sW2[k * 64 + 2 * lane + 1];
#pragma unroll
        for (int r = 0; r < 4; r++) {
            int p = r * CIN + k;
            float xk = (p < 32) ? __shfl_sync(~0u, x0, p) : __shfl_sync(~0u, x1, p - 32);
            u64 h2 = pk2(xk, xk);
            a[r][0] = ffma2(h2, w0, a[r][0]);
            a[r][1] = ffma2(h2, w1, a[r][1]);
        }
    }
#pragma unroll
    for (int r = 0; r < 4; r++) {
        int row = w4 + r;
        if (row < n) {
            float2 v0 = upk2(a[r][0]), v1 = upk2(a[r][1]);
            float4 o;
            o.x = v0.x > 0.f ? v0.x : 0.01f * v0.x;
            o.y = v0.y > 0.f ? v0.y : 0.01f * v0.y;
            o.z = v1.x > 0.f ? v1.x : 0.01f * v1.x;
            o.w = v1.y > 0.f ? v1.y : 0.01f * v1.y;
            *(float4*)(out + (size_t)row * WD + lane * 4) = o;
        }
    }
}

// ---------------- segment min -> maxes (fp-exact transform of segment-max-of-diff) ----------------
__global__ void segmin_kernel(const float* __restrict__ xsrc, const float* __restrict__ xdst,
                              const int* __restrict__ ptr, const int* __restrict__ cnt,
                              const int* __restrict__ csr, float* __restrict__ out, int ndst)
{
    int w = (blockIdx.x * blockDim.x + threadIdx.x) >> 5;
    if (w >= ndst) return;
    int lane = threadIdx.x & 31;
    int deg = __ldg(cnt + w), base = __ldg(ptr + w);
    const float inf = __int_as_float(0x7f800000);
    float4 mn = make_float4(inf, inf, inf, inf);
    int i = 0;
    for (; i + 4 <= deg; i += 4) {
        int s0 = __ldg(csr + base + i), s1 = __ldg(csr + base + i + 1);
        int s2 = __ldg(csr + base + i + 2), s3 = __ldg(csr + base + i + 3);
        float4 v0 = __ldg((const float4*)(xsrc + (size_t)s0 * WD) + lane);
        float4 v1 = __ldg((const float4*)(xsrc + (size_t)s1 * WD) + lane);
        float4 v2 = __ldg((const float4*)(xsrc + (size_t)s2 * WD) + lane);
        float4 v3 = __ldg((const float4*)(xsrc + (size_t)s3 * WD) + lane);
        mn.x = fminf(mn.x, fminf(fminf(v0.x, v1.x), fminf(v2.x, v3.x)));
        mn.y = fminf(mn.y, fminf(fminf(v0.y, v1.y), fminf(v2.y, v3.y)));
        mn.z = fminf(mn.z, fminf(fminf(v0.z, v1.z), fminf(v2.z, v3.z)));
        mn.w = fminf(mn.w, fminf(fminf(v0.w, v1.w), fminf(v2.w, v3.w)));
    }
    for (; i < deg; i++) {
        int s = __ldg(csr + base + i);
        float4 v = __ldg((const float4*)(xsrc + (size_t)s * WD) + lane);
        mn.x = fminf(mn.x, v.x); mn.y = fminf(mn.y, v.y);
        mn.z = fminf(mn.z, v.z); mn.w = fminf(mn.w, v.w);
    }
    float4 o = make_float4(0.f, 0.f, 0.f, 0.f);
    if (deg > 0) {
        float4 a = __ldg((const float4*)(xdst + (size_t)w * WD) + lane);
        o = make_float4(a.x - mn.x, a.y - mn.y, a.z - mn.z, a.w - mn.w);
    }
    ((float4*)(out + (size_t)w * WD))[lane] = o;
}

// ---------------- persistent conv GEMM ----------------
// out = xdst + lrelu([xdst | maxes] @ Wm + bm). W RESIDENT in smem (128KB);
// h streamed as 4 x 64-K chunks per 128-row tile, double-buffered cp.async,
// pipeline runs ACROSS tile boundaries (persistent grid of 148).
// SMEM floats: sW [256][128] resident, sB [128], sH [2][128][68]. 201216 B.
#define CONV_THREADS 256
#define TILE_R 128
#define HSTR 68
#define WFULL (256 * WD)
#define SB_OFF WFULL
#define SH_OFF (WFULL + WD)
#define CONV_SMEM ((SH_OFF + 2 * TILE_R * HSTR) * 4)   // 201216 B

__device__ __forceinline__ void conv_issue_chunk(
    unsigned sHa, const float* xdst, const float* maxbuf, int tile, int c, int n, int tid)
{
    const char* src = (const char*)(c < 2 ? xdst : maxbuf) + (c & 1) * 256;
    unsigned hb = sHa + ((c & 1) * TILE_R * HSTR) * 4;
    int row0 = tile * TILE_R;
#pragma unroll
    for (int t = 0; t < 8; t++) {
        int idx = tid + t * 256;
        int row = idx >> 4, u = idx & 15;
        int sz = (row0 + row < n) ? 16 : 0;
        cp16(hb + row * HSTR * 4 + u * 16, src + (size_t)(row0 + row) * 512 + u * 16, sz);
    }
}

__global__ void __launch_bounds__(CONV_THREADS, 1)
conv_pers(const float* __restrict__ xdst, const float* __restrict__ maxbuf,
          const float* __restrict__ Wm, const float* __restrict__ bm,
          float* __restrict__ out, int n, int ntiles)
{
    extern __shared__ float smem[];
    float* sB = smem + SB_OFF;
    unsigned sWa = (unsigned)__cvta_generic_to_shared(smem);
    unsigned sHa = (unsigned)__cvta_generic_to_shared(smem + SH_OFF);

    int tid = threadIdx.x;
    int bid = blockIdx.x, stride = gridDim.x;
    if (bid >= ntiles) return;

    // prologue: resident W (128KB) + chunk(bid,0) = group0; chunk(bid,1) = group1
    {
        const char* wsrc = (const char*)Wm;
#pragma unroll
        for (int t = 0; t < 32; t++) {
            int u = tid + t * 256;
            cp16(sWa + u * 16, wsrc + u * 16, 16);
        }
        conv_issue_chunk(sHa, xdst, maxbuf, bid, 0, n, tid);
        CP_COMMIT();
        conv_issue_chunk(sHa, xdst, maxbuf, bid, 1, n, tid);
        CP_COMMIT();
    }
    if (tid < WD) sB[tid] = bm[tid];

    int rg = tid >> 3;      // rows rg*4 .. rg*4+3
    int cgp = tid & 7;      // col pairs cgp + 8*cc
    const u64* sB2 = (const u64*)sB;
    u64 acc[4][8];

#pragma unroll 1
    for (int t = bid; t < ntiles; t += stride) {
#pragma unroll 1
        for (int c = 0; c < 4; c++) {
            CP_WAIT1();
            __syncthreads();
            if (c == 0) {
#pragma unroll
                for (int cc = 0; cc < 8; cc++) {
                    u64 b2 = sB2[cgp + 8 * cc];
#pragma unroll
                    for (int r = 0; r < 4; r++) acc[r][cc] = b2;
                }
            }
            const u64* sWc = (const u64*)(smem + c * 8192);      // W rows c*64..
            const float* hb = smem + SH_OFF + (c & 1) * TILE_R * HSTR + (rg * 4) * HSTR;
#pragma unroll 1
            for (int k4 = 0; k4 < 16; k4++) {
                float4 h4[4];
#pragma unroll
                for (int r = 0; r < 4; r++) h4[r] = *(const float4*)(hb + r * HSTR + k4 * 4);
#pragma unroll
                for (int kk = 0; kk < 4; kk++) {
                    const u64* wr = sWc + (k4 * 4 + kk) * 64 + cgp;
                    u64 w[8];
#pragma unroll
                    for (int cc = 0; cc < 8; cc++) w[cc] = wr[8 * cc];
#pragma unroll
                    for (int r = 0; r < 4; r++) {
                        float hv = (kk == 0) ? h4[r].x : (kk == 1) ? h4[r].y
                                 : (kk == 2) ? h4[r].z : h4[r].w;
                        u64 h2 = pk2(hv, hv);
#pragma unroll
                        for (int cc = 0; cc < 8; cc++) acc[r][cc] = ffma2(h2, w[cc], acc[r][cc]);
                    }
                }
            }
            __syncthreads();
            // issue chunk two ahead into the buffer just freed
            int tn = (c < 2) ? t : t + stride;
            int cn = (c < 2) ? c + 2 : c - 2;
            if (tn < ntiles) conv_issue_chunk(sHa, xdst, maxbuf, tn, cn, n, tid);
            CP_COMMIT();
        }
        // epilogue: lrelu + residual, direct coalesced float2 ld/st
        int row0 = t * TILE_R;
#pragma unroll
        for (int r = 0; r < 4; r++) {
            int grow = row0 + rg * 4 + r;
            if (grow < n) {
                const float* xrow = xdst + (size_t)grow * WD;
                float* orow = out + (size_t)grow * WD;
#pragma unroll
                for (int cc = 0; cc < 8; cc++) {
                    int c0 = 2 * (cgp + 8 * cc);
                    float2 v = upk2(acc[r][cc]);
                    float a0 = v.x > 0.f ? v.x : 0.01f * v.x;
                    float a1 = v.y > 0.f ? v.y : 0.01f * v.y;
                    float2 x = __ldg((const float2*)(xrow + c0));
                    float2 res; res.x = x.x + a0; res.y = x.y + a1;
                    *(float2*)(orow + c0) = res;
                }
            }
        }
    }
}

// ---------------- launch ----------------
extern "C" void kernel_launch(void* const* d_in, const int* in_sizes, int n_in,
                              void* d_out, int out_size)
{
    const float* vertices = (const float*)d_in[0];
    const float* edges    = (const float*)d_in[1];
    const float* faces    = (const float*)d_in[2];
    const int* etv_v   = (const int*)d_in[3];
    const int* etv_e   = (const int*)d_in[4];
    const int* fte_e   = (const int*)d_in[5];
    const int* fte_f   = (const int*)d_in[6];
    const int* ftf_src = (const int*)d_in[7];
    const int* ftf_dst = (const int*)d_in[8];
    const float* Wv   = (const float*)d_in[9];
    const float* bv   = (const float*)d_in[10];
    const float* We   = (const float*)d_in[11];
    const float* be   = (const float*)d_in[12];
    const float* Wf   = (const float*)d_in[13];
    const float* bf   = (const float*)d_in[14];
    const float* Wv2e = (const float*)d_in[15];
    const float* bv2e = (const float*)d_in[16];
    const float* We2f = (const float*)d_in[17];
    const float* be2f = (const float*)d_in[18];
    const float* Wm0  = (const float*)d_in[19];
    const float* bm0  = (const float*)d_in[20];
    const float* Wm1  = (const float*)d_in[21];
    const float* bm1  = (const float*)d_in[22];

    float *xv, *xe, *mx;
    int *cnt, *ptr, *csr;
    cudaGetSymbolAddress((void**)&xv, g_xv);
    cudaGetSymbolAddress((void**)&xe, g_xe);
    cudaGetSymbolAddress((void**)&mx, g_max);
    cudaGetSymbolAddress((void**)&cnt, g_cnt);
    cudaGetSymbolAddress((void**)&ptr, g_ptr);
    cudaGetSymbolAddress((void**)&csr, g_csr);
    float* xf = (float*)d_out;

    cudaFuncSetAttribute(conv_pers, cudaFuncAttributeMaxDynamicSharedMemorySize, CONV_SMEM);

    const int NT_E = (NE + TILE_R - 1) / TILE_R;   // 1563
    const int NT_F = (NF + TILE_R - 1) / TILE_R;   // 782

    // 0: all 3 CSRs (index-only)
    build_csr_all<<<148, 1024>>>(etv_v, etv_e, fte_e, fte_f, ftf_src, ftf_dst);

    // 1-3: embeddings
    embed4_kernel<3><<<(NV + 31) / 32, 256>>>(vertices, Wv, bv, xv, NV);
    embed4_kernel<12><<<(NE + 31) / 32, 256>>>(edges, We, be, xe, NE);
    embed4_kernel<14><<<(NF + 31) / 32, 256>>>(faces, Wf, bf, xf, NF);

    // V2E
    segmin_kernel<<<(NE + 7) / 8, 256>>>(xv, xe, ptr, cnt, csr, mx, NE);
    conv_pers<<<148, CONV_THREADS, CONV_SMEM>>>(xe, mx, Wv2e, bv2e, xe, NE, NT_E);

    // E2F
    segmin_kernel<<<(NF + 7) / 8, 256>>>(xe, xf, ptr + NE, cnt + NE, csr, mx, NF);
    conv_pers<<<148, CONV_THREADS, CONV_SMEM>>>(xf, mx, We2f, be2f, xf, NF, NT_F);

    // FF layer 0 (ftf CSR reused)
    segmin_kernel<<<(NF + 7) / 8, 256>>>(xf, xf, ptr + NE + NF, cnt + NE + NF, csr, mx, NF);
    conv_pers<<<148, CONV_THREADS, CONV_SMEM>>>(xf, mx, Wm0, bm0, xf, NF, NT_F);

    // FF layer 1
    segmin_kernel<<<(NF + 7) / 8, 256>>>(xf, xf, ptr + NE + NF, cnt + NE + NF, csr, mx, NF);
    conv_pers<<<148, CONV_THREADS, CONV_SMEM>>>(xf, mx, Wm1, bm1, xf, NF, NT_F);
}